// round 5
// baseline (speedup 1.0000x reference)
#include <cuda_runtime.h>
#include <cstdint>

// Problem constants: B=128, T=2048, D=256, LAMDA=0.5
#define B_ 128
#define T_ 2048
#define D_ 256
#define S_ 32                          // T-splits (chunks) per (b, tensor)
#define ROWS_ITEM (T_ / S_)            // 64 rows per chunk
#define TILE_ROWS 16
#define TILE_FLOATS (TILE_ROWS * D_)   // 4096
#define TILE_BYTES (TILE_FLOATS * 4)   // 16 KB
#define TPI 4                          // tiles per chunk
#define NSTAGE 4
#define NW 8
#define NTHREADS 256
#define GRID_MAIN 444                  // 148 SMs x 3 CTAs, persistent
#define CPT (GRID_MAIN / 2)            // 222 CTAs per tensor type
#define NIT (B_ * S_)                  // 4096 chunks per tensor
#define LOG2E 1.4426950408889634f

// Dynamic smem layout (bytes)
#define SM_DATA 0
#define SM_RED  (NSTAGE * TILE_BYTES)          // 65536 (+8KB)
#define SM_LRED (SM_RED + NW * D_ * 4)         // 73728 (+32B)
#define SM_MBAR (SM_LRED + NW * 4)             // 73760 (8B aligned)
#define SMEM_TOTAL (SM_MBAR + 2 * NSTAGE * 8)  // 73824

// Partials: unnormalized acc[256] + L at [256].
__device__ float g_mids[B_ * D_];
__device__ float g_pa[NIT][258];   // aspect stream
__device__ float g_p1[NIT][258];   // sentiment-sentiment stream
__device__ float g_p2[NIT][258];   // sentiment-aspect stream

__device__ __forceinline__ float warp_sum(float v) {
#pragma unroll
    for (int o = 16; o > 0; o >>= 1) v += __shfl_xor_sync(0xffffffffu, v, o);
    return v;
}
__device__ __forceinline__ uint32_t smem_u32(const void* p) {
    uint32_t a;
    asm("{ .reg .u64 t; cvta.to.shared.u64 t, %1; cvt.u32.u64 %0, t; }"
        : "=r"(a) : "l"(p));
    return a;
}
__device__ __forceinline__ void mbar_init(uint32_t a, uint32_t c) {
    asm volatile("mbarrier.init.shared.b64 [%0], %1;" :: "r"(a), "r"(c) : "memory");
}
__device__ __forceinline__ void mbar_expect_tx(uint32_t a, uint32_t n) {
    asm volatile("mbarrier.arrive.expect_tx.shared.b64 _, [%0], %1;" :: "r"(a), "r"(n) : "memory");
}
__device__ __forceinline__ void mbar_arrive(uint32_t a) {
    asm volatile("mbarrier.arrive.shared.b64 _, [%0];" :: "r"(a) : "memory");
}
__device__ __forceinline__ void mbar_wait(uint32_t a, uint32_t parity) {
    asm volatile(
        "{\n\t.reg .pred P;\n"
        "WL_%=:\n\t"
        "mbarrier.try_wait.parity.acquire.cta.shared::cta.b64 P, [%0], %1, 0x989680;\n\t"
        "@P bra.uni WD_%=;\n\t"
        "bra.uni WL_%=;\n"
        "WD_%=:\n\t}"
        :: "r"(a), "r"(parity) : "memory");
}
__device__ __forceinline__ void bulk_g2s(uint32_t dst, const void* src,
                                         uint32_t bytes, uint32_t mbar) {
    asm volatile(
        "cp.async.bulk.shared::cta.global.mbarrier::complete_tx::bytes [%0], [%1], %2, [%3];"
        :: "r"(dst), "l"(src), "r"(bytes), "r"(mbar) : "memory");
}
__device__ __forceinline__ void fence_async_sc() {
    asm volatile("fence.proxy.async.shared::cta;" ::: "memory");
}
__device__ __forceinline__ float dot8(float4 a, float4 b, float4 c, float4 d) {
    return a.x*b.x + a.y*b.y + a.z*b.z + a.w*b.w
         + c.x*d.x + c.y*d.y + c.z*d.z + c.w*d.w;
}

// ---------------------------------------------------------------------------
// k_mids: g_mids[b] = W_mul @ aspect[b].  1024 CTAs (8 per b), each warp
// computes 4 fully-unrolled rows -> 8 independent loads + 4 reduce chains.
// ---------------------------------------------------------------------------
__global__ void __launch_bounds__(NTHREADS) k_mids(
    const float* __restrict__ aspect, const float* __restrict__ W_mul)
{
    __shared__ __align__(16) float s_asp[D_];
    const int b   = blockIdx.x >> 3;
    const int blk = blockIdx.x & 7;          // 32-row block within D
    const int tid = threadIdx.x;
    const int w   = tid >> 5, lane = tid & 31;

    if (tid < D_) s_asp[tid] = aspect[b * D_ + tid];
    __syncthreads();
    const float4 a0 = *(const float4*)&s_asp[lane * 4];
    const float4 a1 = *(const float4*)&s_asp[128 + lane * 4];

    const int i0 = blk * 32 + w * 4;
    float acc[4];
#pragma unroll
    for (int r = 0; r < 4; r++) {
        const float4* Wr = (const float4*)(W_mul + (size_t)(i0 + r) * D_);
        const float4 x0 = Wr[lane];
        const float4 x1 = Wr[32 + lane];
        acc[r] = dot8(x0, a0, x1, a1);
    }
#pragma unroll
    for (int r = 0; r < 4; r++) acc[r] = warp_sum(acc[r]);
    if (lane < 4) g_mids[b * D_ + i0 + lane] = acc[lane];   // lanes 0-3 hold sums
}

// Wait: warp_sum leaves the full sum in every lane, so lane k holds acc[k]'s
// sum only if we select component k.  Write via lane 0 for each r instead.

// ---------------------------------------------------------------------------
// k_main: persistent; even CTAs stream aspect_memory, odd stream
// sentiment_memory. 4-stage cp.async.bulk pipeline, full/empty mbarriers
// (empty count = NW, one elected arrive per warp). No online max needed:
// aspect scores = tanh in [-1,1]; sentiment scores O(1) -> exp() safe and
// equal to the reference's shifted softmax. Query-side terms cancel.
// ---------------------------------------------------------------------------
__global__ void __launch_bounds__(NTHREADS, 3) k_main(
    const float* __restrict__ sentiment_memory,
    const float* __restrict__ aspect_memory,
    const float* __restrict__ mask,
    const float* __restrict__ b_mul,
    const float* __restrict__ w_ss,
    const float* __restrict__ w_sa)
{
    extern __shared__ __align__(1024) unsigned char dynsmem[];
    float* s_data = (float*)(dynsmem + SM_DATA);
    float* s_red  = (float*)(dynsmem + SM_RED);
    float* s_lred = (float*)(dynsmem + SM_LRED);
    const uint32_t mb_full  = smem_u32(dynsmem + SM_MBAR);
    const uint32_t mb_empty = mb_full + NSTAGE * 8;
    const uint32_t sdata    = smem_u32(s_data);

    const int cta   = blockIdx.x;
    const int ctype = cta & 1;          // 0 = aspect, 1 = sentiment
    const int tcta  = cta >> 1;
    const int tid   = threadIdx.x;
    const int w     = tid >> 5, lane = tid & 31;

    const int nit   = (NIT - tcta + CPT - 1) / CPT;
    const int ntile = nit * TPI;
    const float* membase = ctype ? sentiment_memory : aspect_memory;

    if (tid == 0) {
#pragma unroll
        for (int i = 0; i < NSTAGE; i++) {
            mbar_init(mb_full + i * 8, 1);
            mbar_init(mb_empty + i * 8, NW);
        }
        fence_async_sc();
    }
    __syncthreads();

    int pj = 0, pt = 0;
    const float* pbase = membase
        + ((size_t)(tcta >> 5) * T_ + (size_t)(tcta & 31) * ROWS_ITEM) * D_;
    if (tid == 0) {
#pragma unroll
        for (int i = 0; i < NSTAGE; i++) {   // ntile >= 72 always
            mbar_expect_tx(mb_full + i * 8, TILE_BYTES);
            bulk_g2s(sdata + i * TILE_BYTES, pbase + (size_t)pt * TILE_FLOATS,
                     TILE_BYTES, mb_full + i * 8);
            if (++pt == TPI) {
                pt = 0; pj++;
                if (pj < nit) {
                    const int e2 = tcta + CPT * pj;
                    pbase = membase + ((size_t)(e2 >> 5) * T_
                                     + (size_t)(e2 & 31) * ROWS_ITEM) * D_;
                }
            }
        }
    }

    int gtile = 0, cst = 0, cph = 0;

    if (ctype == 1) {
        // ------------- sentiment: two softmax streams -------------
        // Fold log2(e) into weights: exp(dot(w,r)) = exp2(dot(w*log2e, r)).
        float4 w10 = *(const float4*)(w_ss + lane * 4);
        float4 w11 = *(const float4*)(w_ss + 128 + lane * 4);
        float4 w20 = *(const float4*)(w_sa + lane * 4);
        float4 w21 = *(const float4*)(w_sa + 128 + lane * 4);
        w10.x*=LOG2E; w10.y*=LOG2E; w10.z*=LOG2E; w10.w*=LOG2E;
        w11.x*=LOG2E; w11.y*=LOG2E; w11.z*=LOG2E; w11.w*=LOG2E;
        w20.x*=LOG2E; w20.y*=LOG2E; w20.z*=LOG2E; w20.w*=LOG2E;
        w21.x*=LOG2E; w21.y*=LOG2E; w21.z*=LOG2E; w21.w*=LOG2E;

        for (int j = 0; j < nit; j++) {
            const int e = tcta + CPT * j;
            const int b = e >> 5, s = e & 31;
            const float* mrow = mask + (size_t)b * T_ + s * ROWS_ITEM;

            float l1 = 0.f, l2 = 0.f;
            float4 p0 = {0,0,0,0}, p1 = {0,0,0,0};
            float4 q0 = {0,0,0,0}, q1 = {0,0,0,0};

            for (int t = 0; t < TPI; t++) {
                mbar_wait(mb_full + cst * 8, cph);
                const float* buf = s_data + cst * TILE_FLOATS;
#pragma unroll
                for (int r = 0; r < TILE_ROWS / NW; r++) {
                    const int row = w * (TILE_ROWS / NW) + r;
                    const float4 r0 = *(const float4*)(buf + row * D_ + lane * 4);
                    const float4 r1 = *(const float4*)(buf + row * D_ + 128 + lane * 4);
                    const float mk = mrow[t * TILE_ROWS + row];
                    float d1 = dot8(r0, w10, r1, w11);
                    float d2 = dot8(r0, w20, r1, w21);
#pragma unroll
                    for (int o = 16; o > 0; o >>= 1) {
                        d1 += __shfl_xor_sync(0xffffffffu, d1, o);
                        d2 += __shfl_xor_sync(0xffffffffu, d2, o);
                    }
                    const float pe1 = exp2f(d1) * mk;
                    const float pe2 = exp2f(d2) * mk;
                    l1 += pe1;  l2 += pe2;
                    p0.x += pe1*r0.x; p0.y += pe1*r0.y; p0.z += pe1*r0.z; p0.w += pe1*r0.w;
                    p1.x += pe1*r1.x; p1.y += pe1*r1.y; p1.z += pe1*r1.z; p1.w += pe1*r1.w;
                    q0.x += pe2*r0.x; q0.y += pe2*r0.y; q0.z += pe2*r0.z; q0.w += pe2*r0.w;
                    q1.x += pe2*r1.x; q1.y += pe2*r1.y; q1.z += pe2*r1.z; q1.w += pe2*r1.w;
                }
                if (lane == 0) mbar_arrive(mb_empty + cst * 8);
                if (tid == 0 && gtile + NSTAGE < ntile) {
                    mbar_wait(mb_empty + cst * 8, cph);
                    mbar_expect_tx(mb_full + cst * 8, TILE_BYTES);
                    bulk_g2s(sdata + cst * TILE_BYTES,
                             pbase + (size_t)pt * TILE_FLOATS, TILE_BYTES,
                             mb_full + cst * 8);
                    if (++pt == TPI) {
                        pt = 0; pj++;
                        if (pj < nit) {
                            const int e2 = tcta + CPT * pj;
                            pbase = membase + ((size_t)(e2 >> 5) * T_
                                             + (size_t)(e2 & 31) * ROWS_ITEM) * D_;
                        }
                    }
                }
                gtile++;
                if (++cst == NSTAGE) { cst = 0; cph ^= 1; }
            }

            // flush stream 1
            *(float4*)&s_red[w * D_ + lane * 4]       = p0;
            *(float4*)&s_red[w * D_ + 128 + lane * 4] = p1;
            if (lane == 0) s_lred[w] = l1;
            __syncthreads();
            {
                float v = 0.f, L = 0.f;
#pragma unroll
                for (int ww = 0; ww < NW; ww++) { v += s_red[ww * D_ + tid]; L += s_lred[ww]; }
                g_p1[e][tid] = v;
                if (tid == 0) g_p1[e][256] = L;
            }
            __syncthreads();
            // flush stream 2
            *(float4*)&s_red[w * D_ + lane * 4]       = q0;
            *(float4*)&s_red[w * D_ + 128 + lane * 4] = q1;
            if (lane == 0) s_lred[w] = l2;
            __syncthreads();
            {
                float v = 0.f, L = 0.f;
#pragma unroll
                for (int ww = 0; ww < NW; ww++) { v += s_red[ww * D_ + tid]; L += s_lred[ww]; }
                g_p2[e][tid] = v;
                if (tid == 0) g_p2[e][256] = L;
            }
            __syncthreads();
        }
    } else {
        // ------------- aspect: tanh-score softmax -------------
        const float bm = b_mul[0];
        for (int j = 0; j < nit; j++) {
            const int e = tcta + CPT * j;
            const int b = e >> 5;
            const float4 md0 = *(const float4*)(g_mids + b * D_ + lane * 4);
            const float4 md1 = *(const float4*)(g_mids + b * D_ + 128 + lane * 4);

            float l = 0.f;
            float4 a0 = {0,0,0,0}, a1 = {0,0,0,0};

            for (int t = 0; t < TPI; t++) {
                mbar_wait(mb_full + cst * 8, cph);
                const float* buf = s_data + cst * TILE_FLOATS;
#pragma unroll
                for (int r = 0; r < TILE_ROWS / NW; r++) {
                    const int row = w * (TILE_ROWS / NW) + r;
                    const float4 r0 = *(const float4*)(buf + row * D_ + lane * 4);
                    const float4 r1 = *(const float4*)(buf + row * D_ + 128 + lane * 4);
                    float p = dot8(r0, md0, r1, md1);
                    p = warp_sum(p);
                    const float pe = __expf(tanhf(p + bm));
                    l += pe;
                    a0.x += pe*r0.x; a0.y += pe*r0.y; a0.z += pe*r0.z; a0.w += pe*r0.w;
                    a1.x += pe*r1.x; a1.y += pe*r1.y; a1.z += pe*r1.z; a1.w += pe*r1.w;
                }
                if (lane == 0) mbar_arrive(mb_empty + cst * 8);
                if (tid == 0 && gtile + NSTAGE < ntile) {
                    mbar_wait(mb_empty + cst * 8, cph);
                    mbar_expect_tx(mb_full + cst * 8, TILE_BYTES);
                    bulk_g2s(sdata + cst * TILE_BYTES,
                             pbase + (size_t)pt * TILE_FLOATS, TILE_BYTES,
                             mb_full + cst * 8);
                    if (++pt == TPI) {
                        pt = 0; pj++;
                        if (pj < nit) {
                            const int e2 = tcta + CPT * pj;
                            pbase = membase + ((size_t)(e2 >> 5) * T_
                                             + (size_t)(e2 & 31) * ROWS_ITEM) * D_;
                        }
                    }
                }
                gtile++;
                if (++cst == NSTAGE) { cst = 0; cph ^= 1; }
            }

            *(float4*)&s_red[w * D_ + lane * 4]       = a0;
            *(float4*)&s_red[w * D_ + 128 + lane * 4] = a1;
            if (lane == 0) s_lred[w] = l;
            __syncthreads();
            {
                float v = 0.f, L = 0.f;
#pragma unroll
                for (int ww = 0; ww < NW; ww++) { v += s_red[ww * D_ + tid]; L += s_lred[ww]; }
                g_pa[e][tid] = v;
                if (tid == 0) g_pa[e][256] = L;
            }
            __syncthreads();
        }
    }
}

// ---------------------------------------------------------------------------
// k_combine: 256 CTAs. CTAs [0,128): sentiment_out for b; [128,256): aspect_out.
// d_out: sentiment_out [0, B*D), aspect_out [B*D, 2*B*D).
// ---------------------------------------------------------------------------
__global__ void __launch_bounds__(NTHREADS) k_combine(
    const float* __restrict__ aspect, float* __restrict__ out)
{
    const int b = blockIdx.x & (B_ - 1);
    const int tid = threadIdx.x;
    if (blockIdx.x < B_) {
        float v1 = 0.f, L1 = 0.f, v2 = 0.f, L2 = 0.f;
#pragma unroll 8
        for (int s = 0; s < S_; s++) {
            const int i = b * S_ + s;
            v1 += g_p1[i][tid];  L1 += g_p1[i][256];
            v2 += g_p2[i][tid];  L2 += g_p2[i][256];
        }
        out[b * D_ + tid] = 0.5f * (v1 / L1) + 0.5f * (v2 / L2);
    } else {
        float va = 0.f, La = 0.f;
#pragma unroll 8
        for (int s = 0; s < S_; s++) {
            const int i = b * S_ + s;
            va += g_pa[i][tid];  La += g_pa[i][256];
        }
        out[B_ * D_ + b * D_ + tid] = aspect[b * D_ + tid] + va / La;
    }
}

// ---------------------------------------------------------------------------
// kernel_launch. Inputs (metadata order):
//  0 sentiment  1 aspect  2 sentiment_memory  3 aspect_memory  4 mask
//  5 W_mul  6 b_mul  7 w_ss  8 b_ss  9 w_sa  10 b_sa
// Query-side additive terms (w[D:], biases) cancel in the softmax -> unused.
// ---------------------------------------------------------------------------
extern "C" void kernel_launch(void* const* d_in, const int* in_sizes, int n_in,
                              void* d_out, int out_size)
{
    const float* aspect           = (const float*)d_in[1];
    const float* sentiment_memory = (const float*)d_in[2];
    const float* aspect_memory    = (const float*)d_in[3];
    const float* mask             = (const float*)d_in[4];
    const float* W_mul            = (const float*)d_in[5];
    const float* b_mul            = (const float*)d_in[6];
    const float* w_ss             = (const float*)d_in[7];
    const float* w_sa             = (const float*)d_in[9];
    float* out = (float*)d_out;

    cudaFuncSetAttribute(k_main, cudaFuncAttributeMaxDynamicSharedMemorySize,
                         SMEM_TOTAL);
    k_mids<<<B_ * 8, NTHREADS>>>(aspect, W_mul);
    k_main<<<GRID_MAIN, NTHREADS, SMEM_TOTAL>>>(
        sentiment_memory, aspect_memory, mask, b_mul, w_ss, w_sa);
    k_combine<<<2 * B_, NTHREADS>>>(aspect, out);
}